// round 1
// baseline (speedup 1.0000x reference)
#include <cuda_runtime.h>

#define IMG_H 512
#define IMG_W 512
#define TILE 32
#define HALO 5
#define ITILE (TILE + 2 * HALO)   // 42
#define NPLANES 48                 // 16 * 3
#define NPIX (16LL * 3 * 512 * 512)

__device__ double g_ssim_sum;

__global__ void ssim_zero_kernel() { g_ssim_sum = 0.0; }

__global__ __launch_bounds__(256) void ssim_main_kernel(
    const float* __restrict__ A, const float* __restrict__ B)
{
    __shared__ float sA[ITILE][ITILE + 2];      // 42 x 44
    __shared__ float sB[ITILE][ITILE + 2];
    __shared__ float hh[5][ITILE][TILE + 1];    // 5 x 42 x 33
    __shared__ float warp_sums[8];

    const int tid = threadIdx.x;
    const int plane = blockIdx.z;
    const int tx0 = blockIdx.x * TILE;
    const int ty0 = blockIdx.y * TILE;
    const float* a = A + (size_t)plane * IMG_H * IMG_W;
    const float* b = B + (size_t)plane * IMG_H * IMG_W;

    // Gaussian 1D window (sigma = 1.5, K = 11), normalized. Computed per
    // thread in registers; matches the reference separable 2D window.
    float w[11];
    {
        float s = 0.f;
#pragma unroll
        for (int i = 0; i < 11; i++) {
            float d = (float)(i - 5);
            w[i] = expf(-d * d / 4.5f);   // 2 * 1.5^2 = 4.5
            s += w[i];
        }
        float inv = 1.f / s;
#pragma unroll
        for (int i = 0; i < 11; i++) w[i] *= inv;
    }

    // ---- Load haloed tile (zero padding outside the image) ----
    for (int idx = tid; idx < ITILE * ITILE; idx += 256) {
        int r = idx / ITILE, c = idx % ITILE;
        int gy = ty0 - HALO + r;
        int gx = tx0 - HALO + c;
        float va = 0.f, vb = 0.f;
        if (gy >= 0 && gy < IMG_H && gx >= 0 && gx < IMG_W) {
            size_t o = (size_t)gy * IMG_W + gx;
            va = a[o];
            vb = b[o];
        }
        sA[r][c] = va;
        sB[r][c] = vb;
    }
    __syncthreads();

    // ---- Horizontal 11-tap pass over 5 quantities (A, B, A^2, B^2, AB) ----
    for (int idx = tid; idx < ITILE * TILE; idx += 256) {
        int r = idx / TILE, c = idx % TILE;
        float s1 = 0.f, s2 = 0.f, s11 = 0.f, s22 = 0.f, s12 = 0.f;
#pragma unroll
        for (int k = 0; k < 11; k++) {
            float va = sA[r][c + k];
            float vb = sB[r][c + k];
            float wk = w[k];
            s1  += wk * va;
            s2  += wk * vb;
            s11 += wk * va * va;
            s22 += wk * vb * vb;
            s12 += wk * va * vb;
        }
        hh[0][r][c] = s1;
        hh[1][r][c] = s2;
        hh[2][r][c] = s11;
        hh[3][r][c] = s22;
        hh[4][r][c] = s12;
    }
    __syncthreads();

    // ---- Vertical 11-tap pass + SSIM formula ----
    const float C1 = 0.0001f;   // 0.01^2
    const float C2 = 0.0009f;   // 0.03^2
    float acc = 0.f;
    for (int idx = tid; idx < TILE * TILE; idx += 256) {
        int r = idx / TILE, c = idx % TILE;
        float m1 = 0.f, m2 = 0.f, e11 = 0.f, e22 = 0.f, e12 = 0.f;
#pragma unroll
        for (int k = 0; k < 11; k++) {
            float wk = w[k];
            m1  += wk * hh[0][r + k][c];
            m2  += wk * hh[1][r + k][c];
            e11 += wk * hh[2][r + k][c];
            e22 += wk * hh[3][r + k][c];
            e12 += wk * hh[4][r + k][c];
        }
        float m1s = m1 * m1;
        float m2s = m2 * m2;
        float m12 = m1 * m2;
        float v1  = e11 - m1s;
        float v2  = e22 - m2s;
        float cov = e12 - m12;
        float num = (2.f * m12 + C1) * (2.f * cov + C2);
        float den = (m1s + m2s + C1) * (v1 + v2 + C2);
        acc += num / den;
    }

    // ---- Block reduction, one double atomic per CTA ----
#pragma unroll
    for (int off = 16; off > 0; off >>= 1)
        acc += __shfl_down_sync(0xffffffffu, acc, off);
    if ((tid & 31) == 0) warp_sums[tid >> 5] = acc;
    __syncthreads();
    if (tid < 8) {
        float v = warp_sums[tid];
#pragma unroll
        for (int off = 4; off > 0; off >>= 1)
            v += __shfl_down_sync(0xffu, v, off);
        if (tid == 0) atomicAdd(&g_ssim_sum, (double)v);
    }
}

__global__ void ssim_finalize_kernel(float* __restrict__ out) {
    out[0] = (float)(g_ssim_sum / (double)NPIX);
}

extern "C" void kernel_launch(void* const* d_in, const int* in_sizes, int n_in,
                              void* d_out, int out_size)
{
    const float* A = (const float*)d_in[0];
    const float* B = (const float*)d_in[1];
    float* out = (float*)d_out;

    ssim_zero_kernel<<<1, 1>>>();
    dim3 grid(IMG_W / TILE, IMG_H / TILE, NPLANES);   // 16 x 16 x 48
    ssim_main_kernel<<<grid, 256>>>(A, B);
    ssim_finalize_kernel<<<1, 1>>>(out);
}